// round 15
// baseline (speedup 1.0000x reference)
#include <cuda_runtime.h>
#include <cuda_bf16.h>
#include <cuda_fp16.h>
#include <cstdint>
#include <math.h>

// ---------------------------------------------------------------------------
// IPMTrans round 15:
//   precomp    -> 16B descriptors (fp32 weights)
//   sampler    -> channel-pair packed planes (half2 scale2 / float2 scale4,8)
//   GEMM       -> W-SPLIT FUSED: loads W fp32, converts to bf16 hi/lo in the
//                 A-loader (wsplit kernels deleted, ~235MB DRAM traffic saved)
//                 <64,128> BK=64, 2-stage cp.async for B, warp grid 2x4
//   3 streams  -> per-scale chains
// ---------------------------------------------------------------------------

#define BVAL 2
#define SVAL 4
#define YVAL 4

// ------------------------- scratch (device globals) ------------------------
__device__ __align__(16) __nv_bfloat16 g_v2hi[2u * 1024u * 4096u];
__device__ __align__(16) __nv_bfloat16 g_v2lo[2u * 1024u * 4096u];
__device__ __align__(16) __nv_bfloat16 g_v4hi[2u * 2048u * 1024u];
__device__ __align__(16) __nv_bfloat16 g_v4lo[2u * 2048u * 1024u];
__device__ __align__(16) __nv_bfloat16 g_v8hi[2u * 4096u * 256u];
__device__ __align__(16) __nv_bfloat16 g_v8lo[2u * 4096u * 256u];
__device__ __align__(16) uint4 g_pre2[8u * 16384u];
__device__ __align__(16) uint4 g_pre4[8u * 4096u];
__device__ __align__(16) uint4 g_pre8[8u * 1024u];

// ------------------------- PTX helpers -------------------------------------
__device__ __forceinline__ uint32_t smem_u32(const void* p) {
    uint32_t a;
    asm("{ .reg .u64 t; cvta.to.shared.u64 t, %1; cvt.u32.u64 %0, t; }" : "=r"(a) : "l"(p));
    return a;
}
__device__ __forceinline__ void cp16(uint32_t dst, const void* src) {
    asm volatile("cp.async.cg.shared.global [%0], [%1], 16;" :: "r"(dst), "l"(src));
}
#define CP_COMMIT() asm volatile("cp.async.commit_group;" ::: "memory")
#define CP_WAIT1()  asm volatile("cp.async.wait_group 1;" ::: "memory")

__device__ __forceinline__ void ldsm4(uint32_t* r, uint32_t addr) {
    asm volatile("ldmatrix.sync.aligned.m8n8.x4.shared.b16 {%0,%1,%2,%3}, [%4];"
        : "=r"(r[0]), "=r"(r[1]), "=r"(r[2]), "=r"(r[3]) : "r"(addr));
}
__device__ __forceinline__ void ldsm4t(uint32_t* r, uint32_t addr) {
    asm volatile("ldmatrix.sync.aligned.m8n8.x4.trans.shared.b16 {%0,%1,%2,%3}, [%4];"
        : "=r"(r[0]), "=r"(r[1]), "=r"(r[2]), "=r"(r[3]) : "r"(addr));
}
__device__ __forceinline__ void mma16816(float* d, const uint32_t* a, const uint32_t* b) {
    asm volatile(
        "mma.sync.aligned.m16n8k16.row.col.f32.bf16.bf16.f32 "
        "{%0,%1,%2,%3}, {%4,%5,%6,%7}, {%8,%9}, {%0,%1,%2,%3};"
        : "+f"(d[0]), "+f"(d[1]), "+f"(d[2]), "+f"(d[3])
        : "r"(a[0]), "r"(a[1]), "r"(a[2]), "r"(a[3]), "r"(b[0]), "r"(b[1]));
}

// split one float into bf16 hi/lo ushorts
__device__ __forceinline__ void split_bf16(float f, unsigned short& h, unsigned short& l) {
    __nv_bfloat16 hb = __float2bfloat16(f);
    float r = f - __bfloat162float(hb);
    h = __bfloat16_as_ushort(hb);
    l = __bfloat16_as_ushort(__float2bfloat16(r));
}

// channel-pair pack policies
struct PackF16 {
    using T = __half2;
    static __device__ __forceinline__ T pack(float a, float b) { return __floats2half2_rn(a, b); }
    static __device__ __forceinline__ float2 unpack(T v) { return __half22float2(v); }
};
struct PackF32 {
    using T = float2;
    static __device__ __forceinline__ T pack(float a, float b) { return make_float2(a, b); }
    static __device__ __forceinline__ float2 unpack(T v) { return v; }
};

// ---------------------------------------------------------------------------
// Kernel P: precompute 16B gather descriptors (fp32 weights).
// ---------------------------------------------------------------------------
__global__ void precomp_kernel(const float* __restrict__ coords,
                               uint4* __restrict__ pre,
                               int Wd, int total)
{
    int i = blockIdx.x * blockDim.x + threadIdx.x;
    if (i >= total) return;
    float2 g = ((const float2*)coords)[i];
    const int HW = Wd * Wd;
    const float sc = 0.5f * (float)(Wd - 1);

    float ix = (g.x + 1.0f) * sc;
    float iy = (g.y + 1.0f) * sc;
    float x0f = floorf(ix);
    float y0f = floorf(iy);
    float wx = ix - x0f;
    float wy = iy - y0f;
    int x0 = min(max((int)x0f, 0), Wd - 1);
    int y0 = min(max((int)y0f, 0), Wd - 1);
    int x1 = min(x0 + 1, Wd - 1);
    int y1 = min(y0 + 1, Wd - 1);
    bool valid = (g.x >= -1.0f) & (g.x <= 1.0f) & (g.y >= -1.0f) & (g.y <= 1.0f);

    int a0 = y0 * Wd + x0;
    int a1 = y1 * Wd + x0;
    int dx = x1 - x0;
    if (!valid) { a0 = HW; a1 = HW; dx = 0; wx = 0.0f; wy = 0.0f; }

    pre[i] = make_uint4((uint32_t)a0 | ((uint32_t)dx << 15) | ((uint32_t)a1 << 16),
                        __float_as_uint(wx), __float_as_uint(wy), 0u);
}

// ---------------------------------------------------------------------------
// Kernel 1: channel-pair gather + max over S. grid = (C/2, B), 256 threads.
// ---------------------------------------------------------------------------
template <class PK>
__global__ __launch_bounds__(256) void sample_pair_kernel(
    const float* __restrict__ feat, const uint4* __restrict__ pre,
    __nv_bfloat16* __restrict__ vhi, __nv_bfloat16* __restrict__ vlo,
    int C, int Wd, int ZX)
{
    using T = typename PK::T;
    extern __shared__ char smraw[];
    T* sp = (T*)smraw;

    const int c0 = blockIdx.x * 2;
    const int b = blockIdx.y;
    const int HW = Wd * Wd;
    const int HWP = HW + 4;
    const int N = YVAL * ZX;

    for (int s = 0; s < SVAL; s++) {
        const float4* p0 = (const float4*)(feat + ((size_t)(b * SVAL + s) * C + c0) * (size_t)HW);
        const float4* p1 = (const float4*)(feat + ((size_t)(b * SVAL + s) * C + c0 + 1) * (size_t)HW);
        T* dst = sp + s * HWP;
        for (int i = threadIdx.x; i < HW / 4; i += blockDim.x) {
            float4 A = p0[i];
            float4 B = p1[i];
            dst[i * 4 + 0] = PK::pack(A.x, B.x);
            dst[i * 4 + 1] = PK::pack(A.y, B.y);
            dst[i * 4 + 2] = PK::pack(A.z, B.z);
            dst[i * 4 + 3] = PK::pack(A.w, B.w);
        }
    }
    if (threadIdx.x < SVAL) sp[threadIdx.x * HWP + HW] = PK::pack(0.0f, 0.0f);
    __syncthreads();

    size_t row0 = ((size_t)(b * C + c0) * YVAL) * (size_t)ZX;
    size_t row1 = row0 + (size_t)YVAL * ZX;

    for (int idx = threadIdx.x; idx < N; idx += blockDim.x) {
        float vmax0 = -INFINITY, vmax1 = -INFINITY;
#pragma unroll
        for (int s = 0; s < SVAL; s++) {
            uint4 u = pre[(size_t)(b * SVAL + s) * N + idx];
            int a0 = u.x & 0x7FFF;
            int dx = (u.x >> 15) & 1;
            int a1 = u.x >> 16;
            float wx = __uint_as_float(u.y);
            float wy = __uint_as_float(u.z);
            const T* pl = sp + s * HWP;
            float2 q00 = PK::unpack(pl[a0]);
            float2 q01 = PK::unpack(pl[a0 + dx]);
            float2 q10 = PK::unpack(pl[a1]);
            float2 q11 = PK::unpack(pl[a1 + dx]);
            float v0 = fmaf(wx, q01.x - q00.x, q00.x);
            float v1 = fmaf(wx, q11.x - q10.x, q10.x);
            vmax0 = fmaxf(vmax0, fmaf(wy, v1 - v0, v0));
            float u0 = fmaf(wx, q01.y - q00.y, q00.y);
            float u1 = fmaf(wx, q11.y - q10.y, q10.y);
            vmax1 = fmaxf(vmax1, fmaf(wy, u1 - u0, u0));
        }
        __nv_bfloat16 h0 = __float2bfloat16(vmax0);
        vhi[row0 + idx] = h0;
        vlo[row0 + idx] = __float2bfloat16(vmax0 - __bfloat162float(h0));
        __nv_bfloat16 h1 = __float2bfloat16(vmax1);
        vhi[row1 + idx] = h1;
        vlo[row1 + idx] = __float2bfloat16(vmax1 - __bfloat162float(h1));
    }
}

// ---------------------------------------------------------------------------
// Kernel 2: mma.sync bf16 GEMM + bias + silu, W-split fused into A-loader.
//   W is fp32 [M][K]; loader converts to Ahi/Alo bf16 planes in smem.
//   B (Vhi/Vlo bf16) via cp.async. <64,128> BK=64, 2-stage, warp grid 2x4.
// ---------------------------------------------------------------------------
__global__ __launch_bounds__(256, 2) void gemm_mma_kernel(
    const float* __restrict__ Wf,
    const __nv_bfloat16* __restrict__ Vhi, const __nv_bfloat16* __restrict__ Vlo,
    const float* __restrict__ bias, float* __restrict__ out,
    int M, int N, int K)
{
    constexpr int BM = 64, BN = 128, BK = 64;
    constexpr int WTM = BM / 2;          // 32
    constexpr int WTN = BN / 4;          // 32
    constexpr int MT = WTM / 16;         // 2
    constexpr int NT = WTN / 8;          // 4
    constexpr int ARB = BK * 2;          // 128
    constexpr int CA  = BK / 8;          // 8
    constexpr int A_PLANE = BM * ARB;    // 8192
    constexpr int B_PLANE = BK * BN * 2; // 16384
    constexpr int BRB = BN * 2;          // 256
    constexpr int CB  = BN / 8;          // 16
    constexpr int STAGE = 2 * A_PLANE + 2 * B_PLANE;  // 49152

    extern __shared__ char smraw[];
    const uint32_t sbr = smem_u32(smraw);
    const uint32_t sb = (sbr + 1023u) & ~1023u;
    char* smc = smraw + (sb - sbr);      // CPU-side pointer matching sb

    const int bn = blockIdx.x * BN;
    const int bm = blockIdx.y * BM;
    const int z  = blockIdx.z;
    const int tid = threadIdx.x;
    const int lane = tid & 31;
    const int wid = tid >> 5;
    const int wm = wid & 1;
    const int wn = wid >> 1;

    const __nv_bfloat16* __restrict__ Vhb = Vhi + (size_t)z * (size_t)K * (size_t)N;
    const __nv_bfloat16* __restrict__ Vlb = Vlo + (size_t)z * (size_t)K * (size_t)N;

    float acc[MT][NT][4];
#pragma unroll
    for (int i = 0; i < MT; i++)
#pragma unroll
        for (int j = 0; j < NT; j++)
#pragma unroll
            for (int q = 0; q < 4; q++) acc[i][j][q] = 0.0f;

    const int NC = K / BK;

    // A: LDG fp32 -> split bf16 hi/lo -> STS (fused wsplit). B: cp.async.
    auto load_chunk = [&](int c, int s) {
        char* stc = smc + s * STAGE;
        uint32_t st = sb + (uint32_t)s * STAGE;
        const int k0 = c * BK;
#pragma unroll 2
        for (int i = tid; i < BM * CA; i += 256) {
            int r = i >> 3, ch = i & 7;
            uint32_t off = (uint32_t)(r * ARB + ((ch ^ (r & (CA - 1))) << 4));
            const float4* wp = (const float4*)(Wf + (size_t)(bm + r) * (size_t)K + (size_t)(k0 + ch * 8));
            float4 f0 = wp[0];
            float4 f1 = wp[1];
            unsigned short h[8], l[8];
            split_bf16(f0.x, h[0], l[0]); split_bf16(f0.y, h[1], l[1]);
            split_bf16(f0.z, h[2], l[2]); split_bf16(f0.w, h[3], l[3]);
            split_bf16(f1.x, h[4], l[4]); split_bf16(f1.y, h[5], l[5]);
            split_bf16(f1.z, h[6], l[6]); split_bf16(f1.w, h[7], l[7]);
            uint4 hv = make_uint4((uint32_t)h[0] | ((uint32_t)h[1] << 16),
                                  (uint32_t)h[2] | ((uint32_t)h[3] << 16),
                                  (uint32_t)h[4] | ((uint32_t)h[5] << 16),
                                  (uint32_t)h[6] | ((uint32_t)h[7] << 16));
            uint4 lv = make_uint4((uint32_t)l[0] | ((uint32_t)l[1] << 16),
                                  (uint32_t)l[2] | ((uint32_t)l[3] << 16),
                                  (uint32_t)l[4] | ((uint32_t)l[5] << 16),
                                  (uint32_t)l[6] | ((uint32_t)l[7] << 16));
            *(uint4*)(stc + off) = hv;
            *(uint4*)(stc + A_PLANE + off) = lv;
        }
#pragma unroll 4
        for (int i = tid; i < BK * CB; i += 256) {
            int r = i / CB, ch = i % CB;
            uint32_t off = (uint32_t)(r * BRB + ((ch ^ (r & 7)) << 4));
            size_t g = (size_t)(k0 + r) * (size_t)N + (size_t)(bn + ch * 8);
            cp16(st + 2 * A_PLANE + off, Vhb + g);
            cp16(st + 2 * A_PLANE + B_PLANE + off, Vlb + g);
        }
    };

    load_chunk(0, 0); CP_COMMIT();
    if (NC > 1) load_chunk(1, 1);
    CP_COMMIT();

    uint32_t ahi[2][MT][4], alo[2][MT][4];
    uint32_t bhi[2][NT][2], blo[2][NT][2];

    for (int c = 0; c < NC; c++) {
        CP_WAIT1();
        __syncthreads();

        uint32_t st = sb + (uint32_t)(c & 1) * STAGE;
        uint32_t Ah = st, Al = st + A_PLANE;
        uint32_t Bh = st + 2 * A_PLANE, Bl = Bh + B_PLANE;

        auto load_frags = [&](int ks, int pb) {
#pragma unroll
            for (int mt = 0; mt < MT; mt++) {
                int r = wm * WTM + mt * 16 + (lane & 15);
                int ch = ks * 2 + (lane >> 4);
                uint32_t off = (uint32_t)(r * ARB + ((ch ^ (r & (CA - 1))) << 4));
                ldsm4(ahi[pb][mt], Ah + off);
                ldsm4(alo[pb][mt], Al + off);
            }
#pragma unroll
            for (int nt2 = 0; nt2 < NT / 2; nt2++) {
                int r = ks * 16 + (lane & 15);
                int ch = wn * NT + nt2 * 2 + (lane >> 4);
                uint32_t off = (uint32_t)(r * BRB + ((ch ^ (r & 7)) << 4));
                uint32_t t[4];
                ldsm4t(t, Bh + off);
                bhi[pb][nt2 * 2][0] = t[0]; bhi[pb][nt2 * 2][1] = t[1];
                bhi[pb][nt2 * 2 + 1][0] = t[2]; bhi[pb][nt2 * 2 + 1][1] = t[3];
                ldsm4t(t, Bl + off);
                blo[pb][nt2 * 2][0] = t[0]; blo[pb][nt2 * 2][1] = t[1];
                blo[pb][nt2 * 2 + 1][0] = t[2]; blo[pb][nt2 * 2 + 1][1] = t[3];
            }
        };

        load_frags(0, 0);
#pragma unroll
        for (int ks = 0; ks < BK / 16; ks++) {
            if (ks + 1 < BK / 16) load_frags(ks + 1, (ks + 1) & 1);
            int pb = ks & 1;
#pragma unroll
            for (int mt = 0; mt < MT; mt++)
#pragma unroll
                for (int nt = 0; nt < NT; nt++)
                    mma16816(acc[mt][nt], ahi[pb][mt], bhi[pb][nt]);
#pragma unroll
            for (int mt = 0; mt < MT; mt++)
#pragma unroll
                for (int nt = 0; nt < NT; nt++)
                    mma16816(acc[mt][nt], ahi[pb][mt], blo[pb][nt]);
#pragma unroll
            for (int mt = 0; mt < MT; mt++)
#pragma unroll
                for (int nt = 0; nt < NT; nt++)
                    mma16816(acc[mt][nt], alo[pb][mt], bhi[pb][nt]);
        }
        __syncthreads();

        if (c + 2 < NC) load_chunk(c + 2, c & 1);
        CP_COMMIT();
    }

    float* ob = out + (size_t)z * (size_t)M * (size_t)N;
#pragma unroll
    for (int mt = 0; mt < MT; mt++) {
        int row0 = bm + wm * WTM + mt * 16 + (lane >> 2);
        float bs0 = bias[row0];
        float bs1 = bias[row0 + 8];
#pragma unroll
        for (int nt = 0; nt < NT; nt++) {
            int col = bn + wn * WTN + nt * 8 + (lane & 3) * 2;
            float x0 = acc[mt][nt][0] + bs0;
            float x1 = acc[mt][nt][1] + bs0;
            float x2 = acc[mt][nt][2] + bs1;
            float x3 = acc[mt][nt][3] + bs1;
            float2 r0 = make_float2(x0 / (1.0f + expf(-x0)), x1 / (1.0f + expf(-x1)));
            float2 r1 = make_float2(x2 / (1.0f + expf(-x2)), x3 / (1.0f + expf(-x3)));
            *(float2*)&ob[(size_t)row0 * N + col] = r0;
            *(float2*)&ob[(size_t)(row0 + 8) * N + col] = r1;
        }
    }
}

// ---------------------------------------------------------------------------
// Kernel 3: valid voxel mask from scale-2 coords.
// ---------------------------------------------------------------------------
__global__ void mask_kernel(const float* __restrict__ coords,
                            float* __restrict__ out, int N)
{
    int i = blockIdx.x * blockDim.x + threadIdx.x;
    if (i >= BVAL * N) return;
    int b = i / N;
    int n = i % N;
    const float2* __restrict__ crd = (const float2*)coords;
    float m = 0.0f;
#pragma unroll
    for (int s = 0; s < SVAL; s++) {
        float2 g = crd[(size_t)(b * SVAL + s) * N + n];
        bool valid = (g.x >= -1.0f) & (g.x <= 1.0f) & (g.y >= -1.0f) & (g.y <= 1.0f);
        if (valid) m = 1.0f;
    }
    out[i] = m;
}

// ---------------------------------------------------------------------------
// launch
// ---------------------------------------------------------------------------
extern "C" void kernel_launch(void* const* d_in, const int* in_sizes, int n_in,
                              void* d_out, int out_size)
{
    const float* x3 = (const float*)d_in[0];
    const float* x4 = (const float*)d_in[1];
    const float* x5 = (const float*)d_in[2];
    const float* c2 = (const float*)d_in[3];
    const float* c4 = (const float*)d_in[4];
    const float* c8 = (const float*)d_in[5];
    const float* w2 = (const float*)d_in[6];
    const float* b2 = (const float*)d_in[7];
    const float* w4 = (const float*)d_in[8];
    const float* b4 = (const float*)d_in[9];
    const float* w8 = (const float*)d_in[10];
    const float* b8 = (const float*)d_in[11];

    float* out = (float*)d_out;

    __nv_bfloat16 *v2h, *v2l, *v4h, *v4l, *v8h, *v8l;
    uint4 *p2, *p4, *p8;
    cudaGetSymbolAddress((void**)&v2h, g_v2hi);
    cudaGetSymbolAddress((void**)&v2l, g_v2lo);
    cudaGetSymbolAddress((void**)&v4h, g_v4hi);
    cudaGetSymbolAddress((void**)&v4l, g_v4lo);
    cudaGetSymbolAddress((void**)&v8h, g_v8hi);
    cudaGetSymbolAddress((void**)&v8l, g_v8lo);
    cudaGetSymbolAddress((void**)&p2, g_pre2);
    cudaGetSymbolAddress((void**)&p4, g_pre4);
    cudaGetSymbolAddress((void**)&p8, g_pre8);

    const int smG = 2 * (2 * 64 * 128 + 2 * 64 * 128 * 2) + 1024;
    const int smS2 = 4 * (64 * 64 + 4) * (int)sizeof(__half2);
    const int smS4 = 4 * (32 * 32 + 4) * (int)sizeof(float2);
    const int smS8 = 4 * (16 * 16 + 4) * (int)sizeof(float2);

    static bool s_init = false;
    static cudaStream_t st[3];
    static cudaEvent_t evRoot, evDone[3];
    if (!s_init) {
        for (int i = 0; i < 3; i++)
            cudaStreamCreateWithFlags(&st[i], cudaStreamNonBlocking);
        cudaEventCreateWithFlags(&evRoot, cudaEventDisableTiming);
        for (int i = 0; i < 3; i++)
            cudaEventCreateWithFlags(&evDone[i], cudaEventDisableTiming);
        cudaFuncSetAttribute(sample_pair_kernel<PackF16>,
                             cudaFuncAttributeMaxDynamicSharedMemorySize, 66000);
        cudaFuncSetAttribute(gemm_mma_kernel,
                             cudaFuncAttributeMaxDynamicSharedMemorySize, smG);
        s_init = true;
    }

    const size_t off_bev2 = 0;
    const size_t off_bev4 = off_bev2 + 2ULL * 256 * 4096;
    const size_t off_bev8 = off_bev4 + 2ULL * 512 * 1024;
    const size_t off_mask = off_bev8 + 2ULL * 1024 * 256;

    cudaEventRecord(evRoot, 0);
    for (int i = 0; i < 3; i++) cudaStreamWaitEvent(st[i], evRoot, 0);

    // ---- chain 0: scale 2 ----
    precomp_kernel<<<(8 * 16384 + 255) / 256, 256, 0, st[0]>>>(c2, p2, 64, 8 * 16384);
    sample_pair_kernel<PackF16><<<dim3(256 / 2, BVAL), 256, smS2, st[0]>>>(
        x3, p2, v2h, v2l, 256, 64, 4096);
    gemm_mma_kernel<<<dim3(4096 / 128, 256 / 64, BVAL), 256, smG, st[0]>>>(
        w2, v2h, v2l, b2, out + off_bev2, 256, 4096, 1024);

    // ---- chain 1: scale 4 ----
    precomp_kernel<<<(8 * 4096 + 255) / 256, 256, 0, st[1]>>>(c4, p4, 32, 8 * 4096);
    sample_pair_kernel<PackF32><<<dim3(512 / 2, BVAL), 256, smS4, st[1]>>>(
        x4, p4, v4h, v4l, 512, 32, 1024);
    gemm_mma_kernel<<<dim3(1024 / 128, 512 / 64, BVAL), 256, smG, st[1]>>>(
        w4, v4h, v4l, b4, out + off_bev4, 512, 1024, 2048);

    // ---- chain 2: scale 8 ----
    precomp_kernel<<<(8 * 1024 + 255) / 256, 256, 0, st[2]>>>(c8, p8, 16, 8 * 1024);
    sample_pair_kernel<PackF32><<<dim3(1024 / 2, BVAL), 256, smS8, st[2]>>>(
        x5, p8, v8h, v8l, 1024, 16, 256);
    gemm_mma_kernel<<<dim3(256 / 128, 1024 / 64, BVAL), 256, smG, st[2]>>>(
        w8, v8h, v8l, b8, out + off_bev8, 1024, 256, 4096);

    // mask on the capture stream (independent)
    mask_kernel<<<(BVAL * 16384 + 255) / 256, 256>>>(c2, out + off_mask, 16384);

    for (int i = 0; i < 3; i++) {
        cudaEventRecord(evDone[i], st[i]);
        cudaStreamWaitEvent(0, evDone[i], 0);
    }
}

// round 16
// speedup vs baseline: 1.3177x; 1.3177x over previous
#include <cuda_runtime.h>
#include <cuda_bf16.h>
#include <cuda_fp16.h>
#include <cstdint>
#include <math.h>

// ---------------------------------------------------------------------------
// IPMTrans round 16:
//   numerics   -> W split into fp16 hi/lo (2-pass MMA), V single fp16 plane
//                 (1/3 fewer MMAs, half the B traffic vs bf16 3-pass)
//   precomp    -> 16B descriptors (fp32 weights)
//   sampler    -> channel-pair packed planes, single fp16 output
//   GEMM       -> <64,128> BK=64, 2-stage cp.async, warp grid 2x4
//   3 streams  -> per-scale chains
// ---------------------------------------------------------------------------

#define BVAL 2
#define SVAL 4
#define YVAL 4

// ------------------------- scratch (device globals) ------------------------
__device__ __align__(16) __half g_v2[2u * 1024u * 4096u];
__device__ __align__(16) __half g_v4[2u * 2048u * 1024u];
__device__ __align__(16) __half g_v8[2u * 4096u * 256u];
__device__ __align__(16) __half g_w2hi[256u * 1024u];
__device__ __align__(16) __half g_w2lo[256u * 1024u];
__device__ __align__(16) __half g_w4hi[512u * 2048u];
__device__ __align__(16) __half g_w4lo[512u * 2048u];
__device__ __align__(16) __half g_w8hi[1024u * 4096u];
__device__ __align__(16) __half g_w8lo[1024u * 4096u];
__device__ __align__(16) uint4 g_pre2[8u * 16384u];
__device__ __align__(16) uint4 g_pre4[8u * 4096u];
__device__ __align__(16) uint4 g_pre8[8u * 1024u];

// ------------------------- PTX helpers -------------------------------------
__device__ __forceinline__ uint32_t smem_u32(const void* p) {
    uint32_t a;
    asm("{ .reg .u64 t; cvta.to.shared.u64 t, %1; cvt.u32.u64 %0, t; }" : "=r"(a) : "l"(p));
    return a;
}
__device__ __forceinline__ void cp16(uint32_t dst, const void* src) {
    asm volatile("cp.async.cg.shared.global [%0], [%1], 16;" :: "r"(dst), "l"(src));
}
#define CP_COMMIT() asm volatile("cp.async.commit_group;" ::: "memory")
#define CP_WAIT1()  asm volatile("cp.async.wait_group 1;" ::: "memory")

__device__ __forceinline__ void ldsm4(uint32_t* r, uint32_t addr) {
    asm volatile("ldmatrix.sync.aligned.m8n8.x4.shared.b16 {%0,%1,%2,%3}, [%4];"
        : "=r"(r[0]), "=r"(r[1]), "=r"(r[2]), "=r"(r[3]) : "r"(addr));
}
__device__ __forceinline__ void ldsm4t(uint32_t* r, uint32_t addr) {
    asm volatile("ldmatrix.sync.aligned.m8n8.x4.trans.shared.b16 {%0,%1,%2,%3}, [%4];"
        : "=r"(r[0]), "=r"(r[1]), "=r"(r[2]), "=r"(r[3]) : "r"(addr));
}
__device__ __forceinline__ void mma16816h(float* d, const uint32_t* a, const uint32_t* b) {
    asm volatile(
        "mma.sync.aligned.m16n8k16.row.col.f32.f16.f16.f32 "
        "{%0,%1,%2,%3}, {%4,%5,%6,%7}, {%8,%9}, {%0,%1,%2,%3};"
        : "+f"(d[0]), "+f"(d[1]), "+f"(d[2]), "+f"(d[3])
        : "r"(a[0]), "r"(a[1]), "r"(a[2]), "r"(a[3]), "r"(b[0]), "r"(b[1]));
}

// channel-pair pack policies
struct PackF16 {
    using T = __half2;
    static __device__ __forceinline__ T pack(float a, float b) { return __floats2half2_rn(a, b); }
    static __device__ __forceinline__ float2 unpack(T v) { return __half22float2(v); }
};
struct PackF32 {
    using T = float2;
    static __device__ __forceinline__ T pack(float a, float b) { return make_float2(a, b); }
    static __device__ __forceinline__ float2 unpack(T v) { return v; }
};

// ---------------------------------------------------------------------------
// Kernel P: precompute 16B gather descriptors (fp32 weights).
// ---------------------------------------------------------------------------
__global__ void precomp_kernel(const float* __restrict__ coords,
                               uint4* __restrict__ pre,
                               int Wd, int total)
{
    int i = blockIdx.x * blockDim.x + threadIdx.x;
    if (i >= total) return;
    float2 g = ((const float2*)coords)[i];
    const int HW = Wd * Wd;
    const float sc = 0.5f * (float)(Wd - 1);

    float ix = (g.x + 1.0f) * sc;
    float iy = (g.y + 1.0f) * sc;
    float x0f = floorf(ix);
    float y0f = floorf(iy);
    float wx = ix - x0f;
    float wy = iy - y0f;
    int x0 = min(max((int)x0f, 0), Wd - 1);
    int y0 = min(max((int)y0f, 0), Wd - 1);
    int x1 = min(x0 + 1, Wd - 1);
    int y1 = min(y0 + 1, Wd - 1);
    bool valid = (g.x >= -1.0f) & (g.x <= 1.0f) & (g.y >= -1.0f) & (g.y <= 1.0f);

    int a0 = y0 * Wd + x0;
    int a1 = y1 * Wd + x0;
    int dx = x1 - x0;
    if (!valid) { a0 = HW; a1 = HW; dx = 0; wx = 0.0f; wy = 0.0f; }

    pre[i] = make_uint4((uint32_t)a0 | ((uint32_t)dx << 15) | ((uint32_t)a1 << 16),
                        __float_as_uint(wx), __float_as_uint(wy), 0u);
}

// ---------------------------------------------------------------------------
// Kernel 0: split W fp32 -> fp16 hi/lo (pair represents W to ~2^-21)
// ---------------------------------------------------------------------------
__global__ void wsplit_kernel(const float* __restrict__ w,
                              __half* __restrict__ hi,
                              __half* __restrict__ lo, int n)
{
    int i = blockIdx.x * blockDim.x + threadIdx.x;
    if (i >= n) return;
    float a = w[i];
    __half h = __float2half_rn(a);
    float r = a - __half2float(h);
    hi[i] = h;
    lo[i] = __float2half_rn(r);
}

// ---------------------------------------------------------------------------
// Kernel 1: channel-pair gather + max over S, single fp16 output.
// grid = (C/2, B), 256 threads.
// ---------------------------------------------------------------------------
template <class PK>
__global__ __launch_bounds__(256) void sample_pair_kernel(
    const float* __restrict__ feat, const uint4* __restrict__ pre,
    __half* __restrict__ vout, int C, int Wd, int ZX)
{
    using T = typename PK::T;
    extern __shared__ char smraw[];
    T* sp = (T*)smraw;

    const int c0 = blockIdx.x * 2;
    const int b = blockIdx.y;
    const int HW = Wd * Wd;
    const int HWP = HW + 4;
    const int N = YVAL * ZX;

    for (int s = 0; s < SVAL; s++) {
        const float4* p0 = (const float4*)(feat + ((size_t)(b * SVAL + s) * C + c0) * (size_t)HW);
        const float4* p1 = (const float4*)(feat + ((size_t)(b * SVAL + s) * C + c0 + 1) * (size_t)HW);
        T* dst = sp + s * HWP;
        for (int i = threadIdx.x; i < HW / 4; i += blockDim.x) {
            float4 A = p0[i];
            float4 B = p1[i];
            dst[i * 4 + 0] = PK::pack(A.x, B.x);
            dst[i * 4 + 1] = PK::pack(A.y, B.y);
            dst[i * 4 + 2] = PK::pack(A.z, B.z);
            dst[i * 4 + 3] = PK::pack(A.w, B.w);
        }
    }
    if (threadIdx.x < SVAL) sp[threadIdx.x * HWP + HW] = PK::pack(0.0f, 0.0f);
    __syncthreads();

    size_t row0 = ((size_t)(b * C + c0) * YVAL) * (size_t)ZX;
    size_t row1 = row0 + (size_t)YVAL * ZX;

    for (int idx = threadIdx.x; idx < N; idx += blockDim.x) {
        float vmax0 = -INFINITY, vmax1 = -INFINITY;
#pragma unroll
        for (int s = 0; s < SVAL; s++) {
            uint4 u = pre[(size_t)(b * SVAL + s) * N + idx];
            int a0 = u.x & 0x7FFF;
            int dx = (u.x >> 15) & 1;
            int a1 = u.x >> 16;
            float wx = __uint_as_float(u.y);
            float wy = __uint_as_float(u.z);
            const T* pl = sp + s * HWP;
            float2 q00 = PK::unpack(pl[a0]);
            float2 q01 = PK::unpack(pl[a0 + dx]);
            float2 q10 = PK::unpack(pl[a1]);
            float2 q11 = PK::unpack(pl[a1 + dx]);
            float v0 = fmaf(wx, q01.x - q00.x, q00.x);
            float v1 = fmaf(wx, q11.x - q10.x, q10.x);
            vmax0 = fmaxf(vmax0, fmaf(wy, v1 - v0, v0));
            float u0 = fmaf(wx, q01.y - q00.y, q00.y);
            float u1 = fmaf(wx, q11.y - q10.y, q10.y);
            vmax1 = fmaxf(vmax1, fmaf(wy, u1 - u0, u0));
        }
        vout[row0 + idx] = __float2half_rn(vmax0);
        vout[row1 + idx] = __float2half_rn(vmax1);
    }
}

// ---------------------------------------------------------------------------
// Kernel 2: mma.sync fp16 GEMM + bias + silu, 2-pass (Whi + Wlo vs single V).
// <64,128> BK=64, 2-stage cp.async (64KB, 2 CTAs/SM), warp grid 2x4.
// ---------------------------------------------------------------------------
__global__ __launch_bounds__(256, 2) void gemm_mma_kernel(
    const __half* __restrict__ Whi, const __half* __restrict__ Wlo,
    const __half* __restrict__ V,
    const float* __restrict__ bias, float* __restrict__ out,
    int M, int N, int K)
{
    constexpr int BM = 64, BN = 128, BK = 64;
    constexpr int WTM = BM / 2;          // 32
    constexpr int WTN = BN / 4;          // 32
    constexpr int MT = WTM / 16;         // 2
    constexpr int NT = WTN / 8;          // 4
    constexpr int ARB = BK * 2;          // 128
    constexpr int CA  = BK / 8;          // 8
    constexpr int A_PLANE = BM * ARB;    // 8192
    constexpr int B_PLANE = BK * BN * 2; // 16384
    constexpr int BRB = BN * 2;          // 256
    constexpr int CB  = BN / 8;          // 16
    constexpr int STAGE = 2 * A_PLANE + B_PLANE;  // 32768

    extern __shared__ char smraw[];
    uint32_t sb = (smem_u32(smraw) + 1023u) & ~1023u;

    const int bn = blockIdx.x * BN;
    const int bm = blockIdx.y * BM;
    const int z  = blockIdx.z;
    const int tid = threadIdx.x;
    const int lane = tid & 31;
    const int wid = tid >> 5;
    const int wm = wid & 1;
    const int wn = wid >> 1;

    const __half* __restrict__ Vb = V + (size_t)z * (size_t)K * (size_t)N;

    float acc[MT][NT][4];
#pragma unroll
    for (int i = 0; i < MT; i++)
#pragma unroll
        for (int j = 0; j < NT; j++)
#pragma unroll
            for (int q = 0; q < 4; q++) acc[i][j][q] = 0.0f;

    const int NC = K / BK;

    auto load_chunk = [&](int c, int s) {
        uint32_t st = sb + (uint32_t)s * STAGE;
        const int k0 = c * BK;
#pragma unroll 2
        for (int i = tid; i < BM * CA; i += 256) {
            int r = i >> 3, ch = i & 7;
            uint32_t off = (uint32_t)(r * ARB + ((ch ^ (r & (CA - 1))) << 4));
            size_t g = (size_t)(bm + r) * (size_t)K + (size_t)(k0 + ch * 8);
            cp16(st + off, Whi + g);
            cp16(st + A_PLANE + off, Wlo + g);
        }
#pragma unroll 4
        for (int i = tid; i < BK * CB; i += 256) {
            int r = i / CB, ch = i % CB;
            uint32_t off = (uint32_t)(r * BRB + ((ch ^ (r & 7)) << 4));
            size_t g = (size_t)(k0 + r) * (size_t)N + (size_t)(bn + ch * 8);
            cp16(st + 2 * A_PLANE + off, Vb + g);
        }
    };

    load_chunk(0, 0); CP_COMMIT();
    if (NC > 1) load_chunk(1, 1);
    CP_COMMIT();

    uint32_t ahi[2][MT][4], alo[2][MT][4];
    uint32_t bf[2][NT][2];

    for (int c = 0; c < NC; c++) {
        CP_WAIT1();
        __syncthreads();

        uint32_t st = sb + (uint32_t)(c & 1) * STAGE;
        uint32_t Ah = st, Al = st + A_PLANE;
        uint32_t Bp = st + 2 * A_PLANE;

        auto load_frags = [&](int ks, int pb) {
#pragma unroll
            for (int mt = 0; mt < MT; mt++) {
                int r = wm * WTM + mt * 16 + (lane & 15);
                int ch = ks * 2 + (lane >> 4);
                uint32_t off = (uint32_t)(r * ARB + ((ch ^ (r & (CA - 1))) << 4));
                ldsm4(ahi[pb][mt], Ah + off);
                ldsm4(alo[pb][mt], Al + off);
            }
#pragma unroll
            for (int nt2 = 0; nt2 < NT / 2; nt2++) {
                int r = ks * 16 + (lane & 15);
                int ch = wn * NT + nt2 * 2 + (lane >> 4);
                uint32_t off = (uint32_t)(r * BRB + ((ch ^ (r & 7)) << 4));
                uint32_t t[4];
                ldsm4t(t, Bp + off);
                bf[pb][nt2 * 2][0] = t[0]; bf[pb][nt2 * 2][1] = t[1];
                bf[pb][nt2 * 2 + 1][0] = t[2]; bf[pb][nt2 * 2 + 1][1] = t[3];
            }
        };

        load_frags(0, 0);
#pragma unroll
        for (int ks = 0; ks < BK / 16; ks++) {
            if (ks + 1 < BK / 16) load_frags(ks + 1, (ks + 1) & 1);
            int pb = ks & 1;
#pragma unroll
            for (int mt = 0; mt < MT; mt++)
#pragma unroll
                for (int nt = 0; nt < NT; nt++)
                    mma16816h(acc[mt][nt], ahi[pb][mt], bf[pb][nt]);
#pragma unroll
            for (int mt = 0; mt < MT; mt++)
#pragma unroll
                for (int nt = 0; nt < NT; nt++)
                    mma16816h(acc[mt][nt], alo[pb][mt], bf[pb][nt]);
        }
        __syncthreads();

        if (c + 2 < NC) load_chunk(c + 2, c & 1);
        CP_COMMIT();
    }

    float* ob = out + (size_t)z * (size_t)M * (size_t)N;
#pragma unroll
    for (int mt = 0; mt < MT; mt++) {
        int row0 = bm + wm * WTM + mt * 16 + (lane >> 2);
        float bs0 = bias[row0];
        float bs1 = bias[row0 + 8];
#pragma unroll
        for (int nt = 0; nt < NT; nt++) {
            int col = bn + wn * WTN + nt * 8 + (lane & 3) * 2;
            float x0 = acc[mt][nt][0] + bs0;
            float x1 = acc[mt][nt][1] + bs0;
            float x2 = acc[mt][nt][2] + bs1;
            float x3 = acc[mt][nt][3] + bs1;
            float2 r0 = make_float2(x0 / (1.0f + expf(-x0)), x1 / (1.0f + expf(-x1)));
            float2 r1 = make_float2(x2 / (1.0f + expf(-x2)), x3 / (1.0f + expf(-x3)));
            *(float2*)&ob[(size_t)row0 * N + col] = r0;
            *(float2*)&ob[(size_t)(row0 + 8) * N + col] = r1;
        }
    }
}

// ---------------------------------------------------------------------------
// Kernel 3: valid voxel mask from scale-2 coords.
// ---------------------------------------------------------------------------
__global__ void mask_kernel(const float* __restrict__ coords,
                            float* __restrict__ out, int N)
{
    int i = blockIdx.x * blockDim.x + threadIdx.x;
    if (i >= BVAL * N) return;
    int b = i / N;
    int n = i % N;
    const float2* __restrict__ crd = (const float2*)coords;
    float m = 0.0f;
#pragma unroll
    for (int s = 0; s < SVAL; s++) {
        float2 g = crd[(size_t)(b * SVAL + s) * N + n];
        bool valid = (g.x >= -1.0f) & (g.x <= 1.0f) & (g.y >= -1.0f) & (g.y <= 1.0f);
        if (valid) m = 1.0f;
    }
    out[i] = m;
}

// ---------------------------------------------------------------------------
// launch
// ---------------------------------------------------------------------------
extern "C" void kernel_launch(void* const* d_in, const int* in_sizes, int n_in,
                              void* d_out, int out_size)
{
    const float* x3 = (const float*)d_in[0];
    const float* x4 = (const float*)d_in[1];
    const float* x5 = (const float*)d_in[2];
    const float* c2 = (const float*)d_in[3];
    const float* c4 = (const float*)d_in[4];
    const float* c8 = (const float*)d_in[5];
    const float* w2 = (const float*)d_in[6];
    const float* b2 = (const float*)d_in[7];
    const float* w4 = (const float*)d_in[8];
    const float* b4 = (const float*)d_in[9];
    const float* w8 = (const float*)d_in[10];
    const float* b8 = (const float*)d_in[11];

    float* out = (float*)d_out;

    __half *v2, *v4, *v8;
    __half *w2h, *w2l, *w4h, *w4l, *w8h, *w8l;
    uint4 *p2, *p4, *p8;
    cudaGetSymbolAddress((void**)&v2, g_v2);
    cudaGetSymbolAddress((void**)&v4, g_v4);
    cudaGetSymbolAddress((void**)&v8, g_v8);
    cudaGetSymbolAddress((void**)&w2h, g_w2hi);
    cudaGetSymbolAddress((void**)&w2l, g_w2lo);
    cudaGetSymbolAddress((void**)&w4h, g_w4hi);
    cudaGetSymbolAddress((void**)&w4l, g_w4lo);
    cudaGetSymbolAddress((void**)&w8h, g_w8hi);
    cudaGetSymbolAddress((void**)&w8l, g_w8lo);
    cudaGetSymbolAddress((void**)&p2, g_pre2);
    cudaGetSymbolAddress((void**)&p4, g_pre4);
    cudaGetSymbolAddress((void**)&p8, g_pre8);

    const int smG = 2 * (2 * 64 * 128 + 64 * 128 * 2) + 1024;    // 66560
    const int smS2 = 4 * (64 * 64 + 4) * (int)sizeof(__half2);
    const int smS4 = 4 * (32 * 32 + 4) * (int)sizeof(float2);
    const int smS8 = 4 * (16 * 16 + 4) * (int)sizeof(float2);

    static bool s_init = false;
    static cudaStream_t st[3];
    static cudaEvent_t evRoot, evDone[3];
    if (!s_init) {
        for (int i = 0; i < 3; i++)
            cudaStreamCreateWithFlags(&st[i], cudaStreamNonBlocking);
        cudaEventCreateWithFlags(&evRoot, cudaEventDisableTiming);
        for (int i = 0; i < 3; i++)
            cudaEventCreateWithFlags(&evDone[i], cudaEventDisableTiming);
        cudaFuncSetAttribute(sample_pair_kernel<PackF16>,
                             cudaFuncAttributeMaxDynamicSharedMemorySize, 66000);
        cudaFuncSetAttribute(gemm_mma_kernel,
                             cudaFuncAttributeMaxDynamicSharedMemorySize, smG);
        s_init = true;
    }

    const size_t off_bev2 = 0;
    const size_t off_bev4 = off_bev2 + 2ULL * 256 * 4096;
    const size_t off_bev8 = off_bev4 + 2ULL * 512 * 1024;
    const size_t off_mask = off_bev8 + 2ULL * 1024 * 256;

    cudaEventRecord(evRoot, 0);
    for (int i = 0; i < 3; i++) cudaStreamWaitEvent(st[i], evRoot, 0);

    // ---- chain 0: scale 2 ----
    precomp_kernel<<<(8 * 16384 + 255) / 256, 256, 0, st[0]>>>(c2, p2, 64, 8 * 16384);
    wsplit_kernel<<<(256 * 1024 + 255) / 256, 256, 0, st[0]>>>(w2, w2h, w2l, 256 * 1024);
    sample_pair_kernel<PackF16><<<dim3(256 / 2, BVAL), 256, smS2, st[0]>>>(
        x3, p2, v2, 256, 64, 4096);
    gemm_mma_kernel<<<dim3(4096 / 128, 256 / 64, BVAL), 256, smG, st[0]>>>(
        w2h, w2l, v2, b2, out + off_bev2, 256, 4096, 1024);

    // ---- chain 1: scale 4 ----
    precomp_kernel<<<(8 * 4096 + 255) / 256, 256, 0, st[1]>>>(c4, p4, 32, 8 * 4096);
    wsplit_kernel<<<(512 * 2048 + 255) / 256, 256, 0, st[1]>>>(w4, w4h, w4l, 512 * 2048);
    sample_pair_kernel<PackF32><<<dim3(512 / 2, BVAL), 256, smS4, st[1]>>>(
        x4, p4, v4, 512, 32, 1024);
    gemm_mma_kernel<<<dim3(1024 / 128, 512 / 64, BVAL), 256, smG, st[1]>>>(
        w4h, w4l, v4, b4, out + off_bev4, 512, 1024, 2048);

    // ---- chain 2: scale 8 ----
    precomp_kernel<<<(8 * 1024 + 255) / 256, 256, 0, st[2]>>>(c8, p8, 16, 8 * 1024);
    wsplit_kernel<<<(1024 * 4096 + 255) / 256, 256, 0, st[2]>>>(w8, w8h, w8l, 1024 * 4096);
    sample_pair_kernel<PackF32><<<dim3(1024 / 2, BVAL), 256, smS8, st[2]>>>(
        x5, p8, v8, 1024, 16, 256);
    gemm_mma_kernel<<<dim3(256 / 128, 1024 / 64, BVAL), 256, smG, st[2]>>>(
        w8h, w8l, v8, b8, out + off_bev8, 1024, 256, 4096);

    // mask on the capture stream (independent)
    mask_kernel<<<(BVAL * 16384 + 255) / 256, 256>>>(c2, out + off_mask, 16384);

    for (int i = 0; i < 3; i++) {
        cudaEventRecord(evDone[i], st[i]);
        cudaStreamWaitEvent(0, evDone[i], 0);
    }
}

// round 17
// speedup vs baseline: 1.6026x; 1.2162x over previous
#include <cuda_runtime.h>
#include <cuda_bf16.h>
#include <cuda_fp16.h>
#include <cstdint>
#include <math.h>

// ---------------------------------------------------------------------------
// IPMTrans round 17:
//   numerics   -> W single fp16, V single fp16: 1-pass HMMA GEMM
//                 (error budget: ~3e-4 V-side + ~3e-4 W-side = ~4.4e-4 quad)
//   precomp    -> 16B descriptors (fp32 weights)
//   sampler    -> channel-pair packed planes, fp16 output
//   GEMM       -> <64,128> BK=64, 2-stage cp.async (48KB), warp grid 2x4
//   3 streams  -> per-scale chains
// ---------------------------------------------------------------------------

#define BVAL 2
#define SVAL 4
#define YVAL 4

// ------------------------- scratch (device globals) ------------------------
__device__ __align__(16) __half g_v2[2u * 1024u * 4096u];
__device__ __align__(16) __half g_v4[2u * 2048u * 1024u];
__device__ __align__(16) __half g_v8[2u * 4096u * 256u];
__device__ __align__(16) __half g_w2[256u * 1024u];
__device__ __align__(16) __half g_w4[512u * 2048u];
__device__ __align__(16) __half g_w8[1024u * 4096u];
__device__ __align__(16) uint4 g_pre2[8u * 16384u];
__device__ __align__(16) uint4 g_pre4[8u * 4096u];
__device__ __align__(16) uint4 g_pre8[8u * 1024u];

// ------------------------- PTX helpers -------------------------------------
__device__ __forceinline__ uint32_t smem_u32(const void* p) {
    uint32_t a;
    asm("{ .reg .u64 t; cvta.to.shared.u64 t, %1; cvt.u32.u64 %0, t; }" : "=r"(a) : "l"(p));
    return a;
}
__device__ __forceinline__ void cp16(uint32_t dst, const void* src) {
    asm volatile("cp.async.cg.shared.global [%0], [%1], 16;" :: "r"(dst), "l"(src));
}
#define CP_COMMIT() asm volatile("cp.async.commit_group;" ::: "memory")
#define CP_WAIT1()  asm volatile("cp.async.wait_group 1;" ::: "memory")

__device__ __forceinline__ void ldsm4(uint32_t* r, uint32_t addr) {
    asm volatile("ldmatrix.sync.aligned.m8n8.x4.shared.b16 {%0,%1,%2,%3}, [%4];"
        : "=r"(r[0]), "=r"(r[1]), "=r"(r[2]), "=r"(r[3]) : "r"(addr));
}
__device__ __forceinline__ void ldsm4t(uint32_t* r, uint32_t addr) {
    asm volatile("ldmatrix.sync.aligned.m8n8.x4.trans.shared.b16 {%0,%1,%2,%3}, [%4];"
        : "=r"(r[0]), "=r"(r[1]), "=r"(r[2]), "=r"(r[3]) : "r"(addr));
}
__device__ __forceinline__ void mma16816h(float* d, const uint32_t* a, const uint32_t* b) {
    asm volatile(
        "mma.sync.aligned.m16n8k16.row.col.f32.f16.f16.f32 "
        "{%0,%1,%2,%3}, {%4,%5,%6,%7}, {%8,%9}, {%0,%1,%2,%3};"
        : "+f"(d[0]), "+f"(d[1]), "+f"(d[2]), "+f"(d[3])
        : "r"(a[0]), "r"(a[1]), "r"(a[2]), "r"(a[3]), "r"(b[0]), "r"(b[1]));
}

// channel-pair pack policies
struct PackF16 {
    using T = __half2;
    static __device__ __forceinline__ T pack(float a, float b) { return __floats2half2_rn(a, b); }
    static __device__ __forceinline__ float2 unpack(T v) { return __half22float2(v); }
};
struct PackF32 {
    using T = float2;
    static __device__ __forceinline__ T pack(float a, float b) { return make_float2(a, b); }
    static __device__ __forceinline__ float2 unpack(T v) { return v; }
};

// ---------------------------------------------------------------------------
// Kernel P: precompute 16B gather descriptors (fp32 weights).
// ---------------------------------------------------------------------------
__global__ void precomp_kernel(const float* __restrict__ coords,
                               uint4* __restrict__ pre,
                               int Wd, int total)
{
    int i = blockIdx.x * blockDim.x + threadIdx.x;
    if (i >= total) return;
    float2 g = ((const float2*)coords)[i];
    const int HW = Wd * Wd;
    const float sc = 0.5f * (float)(Wd - 1);

    float ix = (g.x + 1.0f) * sc;
    float iy = (g.y + 1.0f) * sc;
    float x0f = floorf(ix);
    float y0f = floorf(iy);
    float wx = ix - x0f;
    float wy = iy - y0f;
    int x0 = min(max((int)x0f, 0), Wd - 1);
    int y0 = min(max((int)y0f, 0), Wd - 1);
    int x1 = min(x0 + 1, Wd - 1);
    int y1 = min(y0 + 1, Wd - 1);
    bool valid = (g.x >= -1.0f) & (g.x <= 1.0f) & (g.y >= -1.0f) & (g.y <= 1.0f);

    int a0 = y0 * Wd + x0;
    int a1 = y1 * Wd + x0;
    int dx = x1 - x0;
    if (!valid) { a0 = HW; a1 = HW; dx = 0; wx = 0.0f; wy = 0.0f; }

    pre[i] = make_uint4((uint32_t)a0 | ((uint32_t)dx << 15) | ((uint32_t)a1 << 16),
                        __float_as_uint(wx), __float_as_uint(wy), 0u);
}

// ---------------------------------------------------------------------------
// Kernel 0: convert W fp32 -> fp16
// ---------------------------------------------------------------------------
__global__ void wconv_kernel(const float* __restrict__ w,
                             __half* __restrict__ o, int n)
{
    int i = blockIdx.x * blockDim.x + threadIdx.x;
    if (i >= n) return;
    o[i] = __float2half_rn(w[i]);
}

// ---------------------------------------------------------------------------
// Kernel 1: channel-pair gather + max over S, fp16 output.
// grid = (C/2, B), 256 threads.
// ---------------------------------------------------------------------------
template <class PK>
__global__ __launch_bounds__(256) void sample_pair_kernel(
    const float* __restrict__ feat, const uint4* __restrict__ pre,
    __half* __restrict__ vout, int C, int Wd, int ZX)
{
    using T = typename PK::T;
    extern __shared__ char smraw[];
    T* sp = (T*)smraw;

    const int c0 = blockIdx.x * 2;
    const int b = blockIdx.y;
    const int HW = Wd * Wd;
    const int HWP = HW + 4;
    const int N = YVAL * ZX;

    for (int s = 0; s < SVAL; s++) {
        const float4* p0 = (const float4*)(feat + ((size_t)(b * SVAL + s) * C + c0) * (size_t)HW);
        const float4* p1 = (const float4*)(feat + ((size_t)(b * SVAL + s) * C + c0 + 1) * (size_t)HW);
        T* dst = sp + s * HWP;
        for (int i = threadIdx.x; i < HW / 4; i += blockDim.x) {
            float4 A = p0[i];
            float4 B = p1[i];
            dst[i * 4 + 0] = PK::pack(A.x, B.x);
            dst[i * 4 + 1] = PK::pack(A.y, B.y);
            dst[i * 4 + 2] = PK::pack(A.z, B.z);
            dst[i * 4 + 3] = PK::pack(A.w, B.w);
        }
    }
    if (threadIdx.x < SVAL) sp[threadIdx.x * HWP + HW] = PK::pack(0.0f, 0.0f);
    __syncthreads();

    size_t row0 = ((size_t)(b * C + c0) * YVAL) * (size_t)ZX;
    size_t row1 = row0 + (size_t)YVAL * ZX;

    for (int idx = threadIdx.x; idx < N; idx += blockDim.x) {
        float vmax0 = -INFINITY, vmax1 = -INFINITY;
#pragma unroll
        for (int s = 0; s < SVAL; s++) {
            uint4 u = pre[(size_t)(b * SVAL + s) * N + idx];
            int a0 = u.x & 0x7FFF;
            int dx = (u.x >> 15) & 1;
            int a1 = u.x >> 16;
            float wx = __uint_as_float(u.y);
            float wy = __uint_as_float(u.z);
            const T* pl = sp + s * HWP;
            float2 q00 = PK::unpack(pl[a0]);
            float2 q01 = PK::unpack(pl[a0 + dx]);
            float2 q10 = PK::unpack(pl[a1]);
            float2 q11 = PK::unpack(pl[a1 + dx]);
            float v0 = fmaf(wx, q01.x - q00.x, q00.x);
            float v1 = fmaf(wx, q11.x - q10.x, q10.x);
            vmax0 = fmaxf(vmax0, fmaf(wy, v1 - v0, v0));
            float u0 = fmaf(wx, q01.y - q00.y, q00.y);
            float u1 = fmaf(wx, q11.y - q10.y, q10.y);
            vmax1 = fmaxf(vmax1, fmaf(wy, u1 - u0, u0));
        }
        vout[row0 + idx] = __float2half_rn(vmax0);
        vout[row1 + idx] = __float2half_rn(vmax1);
    }
}

// ---------------------------------------------------------------------------
// Kernel 2: mma.sync fp16 GEMM + bias + silu, SINGLE pass (W fp16 x V fp16).
// <64,128> BK=64, 2-stage cp.async (48KB, 2 CTAs/SM), warp grid 2x4.
// ---------------------------------------------------------------------------
__global__ __launch_bounds__(256, 2) void gemm_mma_kernel(
    const __half* __restrict__ Wh, const __half* __restrict__ V,
    const float* __restrict__ bias, float* __restrict__ out,
    int M, int N, int K)
{
    constexpr int BM = 64, BN = 128, BK = 64;
    constexpr int WTM = BM / 2;          // 32
    constexpr int WTN = BN / 4;          // 32
    constexpr int MT = WTM / 16;         // 2
    constexpr int NT = WTN / 8;          // 4
    constexpr int ARB = BK * 2;          // 128
    constexpr int CA  = BK / 8;          // 8
    constexpr int A_PLANE = BM * ARB;    // 8192
    constexpr int B_PLANE = BK * BN * 2; // 16384
    constexpr int BRB = BN * 2;          // 256
    constexpr int CB  = BN / 8;          // 16
    constexpr int STAGE = A_PLANE + B_PLANE;  // 24576

    extern __shared__ char smraw[];
    uint32_t sb = (smem_u32(smraw) + 1023u) & ~1023u;

    const int bn = blockIdx.x * BN;
    const int bm = blockIdx.y * BM;
    const int z  = blockIdx.z;
    const int tid = threadIdx.x;
    const int lane = tid & 31;
    const int wid = tid >> 5;
    const int wm = wid & 1;
    const int wn = wid >> 1;

    const __half* __restrict__ Vb = V + (size_t)z * (size_t)K * (size_t)N;

    float acc[MT][NT][4];
#pragma unroll
    for (int i = 0; i < MT; i++)
#pragma unroll
        for (int j = 0; j < NT; j++)
#pragma unroll
            for (int q = 0; q < 4; q++) acc[i][j][q] = 0.0f;

    const int NC = K / BK;

    auto load_chunk = [&](int c, int s) {
        uint32_t st = sb + (uint32_t)s * STAGE;
        const int k0 = c * BK;
#pragma unroll 2
        for (int i = tid; i < BM * CA; i += 256) {
            int r = i >> 3, ch = i & 7;
            uint32_t off = (uint32_t)(r * ARB + ((ch ^ (r & (CA - 1))) << 4));
            size_t g = (size_t)(bm + r) * (size_t)K + (size_t)(k0 + ch * 8);
            cp16(st + off, Wh + g);
        }
#pragma unroll 4
        for (int i = tid; i < BK * CB; i += 256) {
            int r = i / CB, ch = i % CB;
            uint32_t off = (uint32_t)(r * BRB + ((ch ^ (r & 7)) << 4));
            size_t g = (size_t)(k0 + r) * (size_t)N + (size_t)(bn + ch * 8);
            cp16(st + A_PLANE + off, Vb + g);
        }
    };

    load_chunk(0, 0); CP_COMMIT();
    if (NC > 1) load_chunk(1, 1);
    CP_COMMIT();

    uint32_t af[2][MT][4];
    uint32_t bf[2][NT][2];

    for (int c = 0; c < NC; c++) {
        CP_WAIT1();
        __syncthreads();

        uint32_t st = sb + (uint32_t)(c & 1) * STAGE;
        uint32_t Ap = st;
        uint32_t Bp = st + A_PLANE;

        auto load_frags = [&](int ks, int pb) {
#pragma unroll
            for (int mt = 0; mt < MT; mt++) {
                int r = wm * WTM + mt * 16 + (lane & 15);
                int ch = ks * 2 + (lane >> 4);
                uint32_t off = (uint32_t)(r * ARB + ((ch ^ (r & (CA - 1))) << 4));
                ldsm4(af[pb][mt], Ap + off);
            }
#pragma unroll
            for (int nt2 = 0; nt2 < NT / 2; nt2++) {
                int r = ks * 16 + (lane & 15);
                int ch = wn * NT + nt2 * 2 + (lane >> 4);
                uint32_t off = (uint32_t)(r * BRB + ((ch ^ (r & 7)) << 4));
                uint32_t t[4];
                ldsm4t(t, Bp + off);
                bf[pb][nt2 * 2][0] = t[0]; bf[pb][nt2 * 2][1] = t[1];
                bf[pb][nt2 * 2 + 1][0] = t[2]; bf[pb][nt2 * 2 + 1][1] = t[3];
            }
        };

        load_frags(0, 0);
#pragma unroll
        for (int ks = 0; ks < BK / 16; ks++) {
            if (ks + 1 < BK / 16) load_frags(ks + 1, (ks + 1) & 1);
            int pb = ks & 1;
#pragma unroll
            for (int mt = 0; mt < MT; mt++)
#pragma unroll
                for (int nt = 0; nt < NT; nt++)
                    mma16816h(acc[mt][nt], af[pb][mt], bf[pb][nt]);
        }
        __syncthreads();

        if (c + 2 < NC) load_chunk(c + 2, c & 1);
        CP_COMMIT();
    }

    float* ob = out + (size_t)z * (size_t)M * (size_t)N;
#pragma unroll
    for (int mt = 0; mt < MT; mt++) {
        int row0 = bm + wm * WTM + mt * 16 + (lane >> 2);
        float bs0 = bias[row0];
        float bs1 = bias[row0 + 8];
#pragma unroll
        for (int nt = 0; nt < NT; nt++) {
            int col = bn + wn * WTN + nt * 8 + (lane & 3) * 2;
            float x0 = acc[mt][nt][0] + bs0;
            float x1 = acc[mt][nt][1] + bs0;
            float x2 = acc[mt][nt][2] + bs1;
            float x3 = acc[mt][nt][3] + bs1;
            float2 r0 = make_float2(x0 / (1.0f + expf(-x0)), x1 / (1.0f + expf(-x1)));
            float2 r1 = make_float2(x2 / (1.0f + expf(-x2)), x3 / (1.0f + expf(-x3)));
            *(float2*)&ob[(size_t)row0 * N + col] = r0;
            *(float2*)&ob[(size_t)(row0 + 8) * N + col] = r1;
        }
    }
}

// ---------------------------------------------------------------------------
// Kernel 3: valid voxel mask from scale-2 coords.
// ---------------------------------------------------------------------------
__global__ void mask_kernel(const float* __restrict__ coords,
                            float* __restrict__ out, int N)
{
    int i = blockIdx.x * blockDim.x + threadIdx.x;
    if (i >= BVAL * N) return;
    int b = i / N;
    int n = i % N;
    const float2* __restrict__ crd = (const float2*)coords;
    float m = 0.0f;
#pragma unroll
    for (int s = 0; s < SVAL; s++) {
        float2 g = crd[(size_t)(b * SVAL + s) * N + n];
        bool valid = (g.x >= -1.0f) & (g.x <= 1.0f) & (g.y >= -1.0f) & (g.y <= 1.0f);
        if (valid) m = 1.0f;
    }
    out[i] = m;
}

// ---------------------------------------------------------------------------
// launch
// ---------------------------------------------------------------------------
extern "C" void kernel_launch(void* const* d_in, const int* in_sizes, int n_in,
                              void* d_out, int out_size)
{
    const float* x3 = (const float*)d_in[0];
    const float* x4 = (const float*)d_in[1];
    const float* x5 = (const float*)d_in[2];
    const float* c2 = (const float*)d_in[3];
    const float* c4 = (const float*)d_in[4];
    const float* c8 = (const float*)d_in[5];
    const float* w2 = (const float*)d_in[6];
    const float* b2 = (const float*)d_in[7];
    const float* w4 = (const float*)d_in[8];
    const float* b4 = (const float*)d_in[9];
    const float* w8 = (const float*)d_in[10];
    const float* b8 = (const float*)d_in[11];

    float* out = (float*)d_out;

    __half *v2, *v4, *v8, *w2h, *w4h, *w8h;
    uint4 *p2, *p4, *p8;
    cudaGetSymbolAddress((void**)&v2, g_v2);
    cudaGetSymbolAddress((void**)&v4, g_v4);
    cudaGetSymbolAddress((void**)&v8, g_v8);
    cudaGetSymbolAddress((void**)&w2h, g_w2);
    cudaGetSymbolAddress((void**)&w4h, g_w4);
    cudaGetSymbolAddress((void**)&w8h, g_w8);
    cudaGetSymbolAddress((void**)&p2, g_pre2);
    cudaGetSymbolAddress((void**)&p4, g_pre4);
    cudaGetSymbolAddress((void**)&p8, g_pre8);

    const int smG = 2 * (64 * 128 + 64 * 128 * 2) + 1024;        // 50176
    const int smS2 = 4 * (64 * 64 + 4) * (int)sizeof(__half2);
    const int smS4 = 4 * (32 * 32 + 4) * (int)sizeof(float2);
    const int smS8 = 4 * (16 * 16 + 4) * (int)sizeof(float2);

    static bool s_init = false;
    static cudaStream_t st[3];
    static cudaEvent_t evRoot, evDone[3];
    if (!s_init) {
        for (int i = 0; i < 3; i++)
            cudaStreamCreateWithFlags(&st[i], cudaStreamNonBlocking);
        cudaEventCreateWithFlags(&evRoot, cudaEventDisableTiming);
        for (int i = 0; i < 3; i++)
            cudaEventCreateWithFlags(&evDone[i], cudaEventDisableTiming);
        cudaFuncSetAttribute(sample_pair_kernel<PackF16>,
                             cudaFuncAttributeMaxDynamicSharedMemorySize, 66000);
        cudaFuncSetAttribute(gemm_mma_kernel,
                             cudaFuncAttributeMaxDynamicSharedMemorySize, smG);
        s_init = true;
    }

    const size_t off_bev2 = 0;
    const size_t off_bev4 = off_bev2 + 2ULL * 256 * 4096;
    const size_t off_bev8 = off_bev4 + 2ULL * 512 * 1024;
    const size_t off_mask = off_bev8 + 2ULL * 1024 * 256;

    cudaEventRecord(evRoot, 0);
    for (int i = 0; i < 3; i++) cudaStreamWaitEvent(st[i], evRoot, 0);

    // ---- chain 0: scale 2 ----
    precomp_kernel<<<(8 * 16384 + 255) / 256, 256, 0, st[0]>>>(c2, p2, 64, 8 * 16384);
    wconv_kernel<<<(256 * 1024 + 255) / 256, 256, 0, st[0]>>>(w2, w2h, 256 * 1024);
    sample_pair_kernel<PackF16><<<dim3(256 / 2, BVAL), 256, smS2, st[0]>>>(
        x3, p2, v2, 256, 64, 4096);
    gemm_mma_kernel<<<dim3(4096 / 128, 256 / 64, BVAL), 256, smG, st[0]>>>(
        w2h, v2, b2, out + off_bev2, 256, 4096, 1024);

    // ---- chain 1: scale 4 ----
    precomp_kernel<<<(8 * 4096 + 255) / 256, 256, 0, st[1]>>>(c4, p4, 32, 8 * 4096);
    wconv_kernel<<<(512 * 2048 + 255) / 256, 256, 0, st[1]>>>(w4, w4h, 512 * 2048);
    sample_pair_kernel<PackF32><<<dim3(512 / 2, BVAL), 256, smS4, st[1]>>>(
        x4, p4, v4, 512, 32, 1024);
    gemm_mma_kernel<<<dim3(1024 / 128, 512 / 64, BVAL), 256, smG, st[1]>>>(
        w4h, v4, b4, out + off_bev4, 512, 1024, 2048);

    // ---- chain 2: scale 8 ----
    precomp_kernel<<<(8 * 1024 + 255) / 256, 256, 0, st[2]>>>(c8, p8, 16, 8 * 1024);
    wconv_kernel<<<(1024 * 4096 + 255) / 256, 256, 0, st[2]>>>(w8, w8h, 1024 * 4096);
    sample_pair_kernel<PackF32><<<dim3(1024 / 2, BVAL), 256, smS8, st[2]>>>(
        x5, p8, v8, 1024, 16, 256);
    gemm_mma_kernel<<<dim3(256 / 128, 1024 / 64, BVAL), 256, smG, st[2]>>>(
        w8h, v8, b8, out + off_bev8, 1024, 256, 4096);

    // mask on the capture stream (independent)
    mask_kernel<<<(BVAL * 16384 + 255) / 256, 256>>>(c2, out + off_mask, 16384);

    for (int i = 0; i < 3; i++) {
        cudaEventRecord(evDone[i], st[i]);
        cudaStreamWaitEvent(0, evDone[i], 0);
    }
}